// round 3
// baseline (speedup 1.0000x reference)
#include <cuda_runtime.h>
#include <cstdint>

#define R        128
#define R3       (R * R * R)
#define BATCH    2
#define NV_TOT   7700
#define NSURF_N  6890
#define NT_TOT   30000
#define EPS_W    0.001f
#define INV2SIG2 200.0f   // 1/(2*0.05^2)

// Scratch: per-voxel occupancy byte and interleaved accumulator
// acc = (sem0, sem1, sem2, wsum)
__device__ unsigned char g_occ[BATCH * R3];
__device__ float4        g_acc[BATCH * R3];

__device__ __forceinline__ void red_add_f32x4(float4* addr, float x, float y,
                                              float z, float w) {
    asm volatile("red.global.add.v4.f32 [%0], {%1, %2, %3, %4};"
                 :: "l"(addr), "f"(x), "f"(y), "f"(z), "f"(w)
                 : "memory");
}

// ---------------------------------------------------------------------------
// init_acc: acc = (0,0,0,EPS_W); 4 float4 per thread.
// ---------------------------------------------------------------------------
__global__ void init_acc_kernel() {
    int i = blockIdx.x * blockDim.x + threadIdx.x;
    if (i >= BATCH * R3 / 4) return;
    float4 z = make_float4(0.0f, 0.0f, 0.0f, EPS_W);
    float4* a = g_acc + (size_t)i * 4;
    a[0] = z; a[1] = z; a[2] = z; a[3] = z;
}

// ---------------------------------------------------------------------------
// init_occ: occ = 0; 16 bytes per thread.
// ---------------------------------------------------------------------------
__global__ void init_occ_kernel() {
    int i = blockIdx.x * blockDim.x + threadIdx.x;
    if (i >= BATCH * R3 / 16) return;
    ((uint4*)g_occ)[i] = make_uint4(0u, 0u, 0u, 0u);
}

// ---------------------------------------------------------------------------
// tet occupancy: ONE WARP per (b, tet). Setup computed once per warp;
// 32 lanes sweep the 5^3 = 125 window in 4 strided passes.
// ---------------------------------------------------------------------------
__global__ void tet_kernel(const float* __restrict__ verts,
                           const int*   __restrict__ tets) {
    int gw   = (blockIdx.x * blockDim.x + threadIdx.x) >> 5;  // global warp
    int lane = threadIdx.x & 31;
    if (gw >= BATCH * NT_TOT) return;
    int b = gw / NT_TOT;
    int t = gw - b * NT_TOT;

    int4 ti = ((const int4*)tets)[t];
    const float* vb = verts + (size_t)b * NV_TOT * 3;
    const float* p0 = vb + (size_t)ti.x * 3;
    const float* p1 = vb + (size_t)ti.y * 3;
    const float* p2 = vb + (size_t)ti.z * 3;
    const float* p3 = vb + (size_t)ti.w * 3;

    float ax = p0[0], ay = p0[1], az = p0[2];
    float bxv = p1[0], byv = p1[1], bzv = p1[2];
    float cxv = p2[0], cyv = p2[1], czv = p2[2];
    float dxv = p3[0], dyv = p3[1], dzv = p3[2];

    float e1x = bxv - ax, e1y = byv - ay, e1z = bzv - az;
    float e2x = cxv - ax, e2y = cyv - ay, e2z = czv - az;
    float e3x = dxv - ax, e3y = dyv - ay, e3z = dzv - az;

    float c23x = e2y * e3z - e2z * e3y;
    float c23y = e2z * e3x - e2x * e3z;
    float c23z = e2x * e3y - e2y * e3x;

    float vol6 = e1x * c23x + e1y * c23y + e1z * c23z;
    bool volok = fabsf(vol6) > 1e-12f;
    if (!volok) return;
    float iv = 1.0f / vol6;

    int anx  = (int)floorf(fminf(fminf(ax, bxv), fminf(cxv, dxv)) * (float)R);
    int any_ = (int)floorf(fminf(fminf(ay, byv), fminf(cyv, dyv)) * (float)R);
    int anz  = (int)floorf(fminf(fminf(az, bzv), fminf(czv, dzv)) * (float)R);

    unsigned char* occb = g_occ + b * R3;

    #pragma unroll
    for (int k = 0; k < 4; k++) {
        int j = lane + k * 32;
        if (j >= 125) break;
        int t0 = anx + j / 25;
        int t1 = any_ + (j / 5) % 5;
        int t2 = anz + j % 5;
        if ((unsigned)t0 >= R || (unsigned)t1 >= R || (unsigned)t2 >= R) continue;

        float px = ((float)t0 + 0.5f) * (1.0f / (float)R) - ax;
        float py = ((float)t1 + 0.5f) * (1.0f / (float)R) - ay;
        float pz = ((float)t2 + 0.5f) * (1.0f / (float)R) - az;

        float l1 = (px * c23x + py * c23y + pz * c23z) * iv;

        float q1x = py * e3z - pz * e3y;
        float q1y = pz * e3x - px * e3z;
        float q1z = px * e3y - py * e3x;
        float l2 = (q1x * e1x + q1y * e1y + q1z * e1z) * iv;

        float q2x = e2y * pz - e2z * py;
        float q2y = e2z * px - e2x * pz;
        float q2z = e2x * py - e2y * px;
        float l3 = (q2x * e1x + q2y * e1y + q2z * e1z) * iv;

        if (l1 >= 0.0f && l2 >= 0.0f && l3 >= 0.0f && (l1 + l2 + l3) <= 1.0f) {
            occb[(t2 * R + t1) * R + t0] = 1;
        }
    }
}

// ---------------------------------------------------------------------------
// surface splat: ONE WARP per (b, vertex). Setup once per warp; 32 lanes
// sweep the 7^3 = 343 window in 11 strided passes. One float4 vector
// reduction per voxel: (w*c0, w*c1, w*c2, w).
// ---------------------------------------------------------------------------
__global__ void splat_kernel(const float* __restrict__ verts,
                             const float* __restrict__ code) {
    int gw   = (blockIdx.x * blockDim.x + threadIdx.x) >> 5;
    int lane = threadIdx.x & 31;
    if (gw >= BATCH * NSURF_N) return;
    int b = gw / NSURF_N;
    int v = gw - b * NSURF_N;

    const float* vp = verts + ((size_t)b * NV_TOT + v) * 3;
    float vx = vp[0], vy = vp[1], vz = vp[2];
    const float* cp = code + ((size_t)b * NSURF_N + v) * 3;
    float c0 = cp[0], c1 = cp[1], c2 = cp[2];

    int bx = (int)floorf(vx * (float)R);
    int by = (int)floorf(vy * (float)R);
    int bz = (int)floorf(vz * (float)R);

    float4* accb = g_acc + b * R3;

    #pragma unroll 4
    for (int k = 0; k < 11; k++) {
        int j = lane + k * 32;
        if (j >= 343) break;
        int s0 = bx + j / 49 - 3;
        int s1 = by + (j / 7) % 7 - 3;
        int s2 = bz + j % 7 - 3;
        if ((unsigned)s0 >= R || (unsigned)s1 >= R || (unsigned)s2 >= R) continue;

        float dx = ((float)s0 + 0.5f) * (1.0f / (float)R) - vx;
        float dy = ((float)s1 + 0.5f) * (1.0f / (float)R) - vy;
        float dz = ((float)s2 + 0.5f) * (1.0f / (float)R) - vz;
        float d2 = dx * dx + dy * dy + dz * dz;
        float w = __expf(-d2 * INV2SIG2);

        int vox = (s2 * R + s1) * R + s0;
        red_add_f32x4(&accb[vox], w * c0, w * c1, w * c2, w);
    }
}

// ---------------------------------------------------------------------------
// finalize: out[b,c,vox] = acc.c / acc.w * occ. 4 voxels per thread.
// ---------------------------------------------------------------------------
__global__ void finalize_kernel(float* __restrict__ out) {
    int i = blockIdx.x * blockDim.x + threadIdx.x;   // 4-voxel group
    if (i >= BATCH * R3 / 4) return;
    int gi  = i * 4;
    int b   = gi >> 21;
    int vox = gi & (R3 - 1);

    uchar4 oc = ((const uchar4*)g_occ)[i];
    const float4* a = g_acc + gi;
    float4 a0 = a[0], a1 = a[1], a2 = a[2], a3 = a[3];

    float s0 = (float)oc.x / a0.w;
    float s1 = (float)oc.y / a1.w;
    float s2 = (float)oc.z / a2.w;
    float s3 = (float)oc.w / a3.w;

    float* ob = out + (size_t)b * 3 * R3 + vox;
    *(float4*)(ob)          = make_float4(a0.x * s0, a1.x * s1, a2.x * s2, a3.x * s3);
    *(float4*)(ob + R3)     = make_float4(a0.y * s0, a1.y * s1, a2.y * s2, a3.y * s3);
    *(float4*)(ob + 2 * R3) = make_float4(a0.z * s0, a1.z * s1, a2.z * s2, a3.z * s3);
}

// ---------------------------------------------------------------------------
extern "C" void kernel_launch(void* const* d_in, const int* in_sizes, int n_in,
                              void* d_out, int out_size) {
    const float* smpl_vertices = (const float*)d_in[0]; // (2, 7700, 3)
    const float* vertex_code   = (const float*)d_in[1]; // (2, 6890, 3)
    // d_in[2] = face_indices — dead code in the reference, unused.
    const int*   tet_indices   = (const int*)d_in[3];   // (30000, 4)
    float* out = (float*)d_out;                         // (2, 3, 128, 128, 128)

    // Side stream + events created once (host-side resources only; no device
    // memory). Creation happens on the uncaptured correctness call first.
    static cudaStream_t s_side = nullptr;
    static cudaEvent_t  s_evFork = nullptr, s_evJoin = nullptr;
    if (s_side == nullptr) {
        cudaStreamCreateWithFlags(&s_side, cudaStreamNonBlocking);
        cudaEventCreateWithFlags(&s_evFork, cudaEventDisableTiming);
        cudaEventCreateWithFlags(&s_evJoin, cudaEventDisableTiming);
    }

    // Fork: chain B (occ init -> tet) on side stream, chain A (acc init ->
    // splat) on the main/capture stream. Join before finalize.
    cudaEventRecord(s_evFork, 0);
    cudaStreamWaitEvent(s_side, s_evFork, 0);

    // chain B on side stream
    {
        int n = BATCH * R3 / 16;
        init_occ_kernel<<<(n + 255) / 256, 256, 0, s_side>>>();
        int warps = BATCH * NT_TOT;                       // one warp per tet
        tet_kernel<<<(warps * 32 + 255) / 256, 256, 0, s_side>>>(smpl_vertices,
                                                                 tet_indices);
        cudaEventRecord(s_evJoin, s_side);
    }

    // chain A on main stream
    {
        int n = BATCH * R3 / 4;
        init_acc_kernel<<<(n + 255) / 256, 256>>>();
        int warps = BATCH * NSURF_N;                      // one warp per vertex
        splat_kernel<<<(warps * 32 + 255) / 256, 256>>>(smpl_vertices,
                                                        vertex_code);
    }

    cudaStreamWaitEvent(0, s_evJoin, 0);
    {
        int n = BATCH * R3 / 4;
        finalize_kernel<<<(n + 255) / 256, 256>>>(out);
    }
}

// round 4
// speedup vs baseline: 1.5472x; 1.5472x over previous
#include <cuda_runtime.h>
#include <cstdint>

#define R        128
#define R3       (R * R * R)
#define BATCH    2
#define NV_TOT   7700
#define NSURF_N  6890
#define NT_TOT   30000
#define EPS_W    0.001f
#define INV2SIG2 200.0f   // 1/(2*0.05^2)

#define TPB         256
#define TETS_PER_BLK 8                                  // one warp per tet
#define TET_BLOCKS  ((BATCH * NT_TOT + TETS_PER_BLK - 1) / TETS_PER_BLK) // 7500
#define SPLAT_BLOCKS (BATCH * NSURF_N)                  // one vertex per block

// Scratch: per-voxel occupancy byte and interleaved accumulator
// acc = (sem0, sem1, sem2, wsum)
__device__ unsigned char g_occ[BATCH * R3];
__device__ float4        g_acc[BATCH * R3];

__device__ __forceinline__ void red_add_f32x4(float4* addr, float x, float y,
                                              float z, float w) {
    asm volatile("red.global.add.v4.f32 [%0], {%1, %2, %3, %4};"
                 :: "l"(addr), "f"(x), "f"(y), "f"(z), "f"(w)
                 : "memory");
}

// ---------------------------------------------------------------------------
// init: occ = 0 and acc = (0,0,0,EPS_W) in one kernel.
// Thread i handles 4 float4 of acc and 16 bytes of occ.
// ---------------------------------------------------------------------------
__global__ void init_kernel() {
    int i = blockIdx.x * blockDim.x + threadIdx.x;
    if (i < BATCH * R3 / 16)
        ((uint4*)g_occ)[i] = make_uint4(0u, 0u, 0u, 0u);
    if (i >= BATCH * R3 / 4) return;
    float4 z = make_float4(0.0f, 0.0f, 0.0f, EPS_W);
    float4* a = g_acc + (size_t)i * 4;
    a[0] = z; a[1] = z; a[2] = z; a[3] = z;
}

// ---------------------------------------------------------------------------
// tet occupancy, warp-granular: one warp per (b, tet).
// ---------------------------------------------------------------------------
__device__ __forceinline__ void tet_work(int gw, int lane,
                                         const float* __restrict__ verts,
                                         const int*   __restrict__ tets) {
    int b = gw / NT_TOT;
    int t = gw - b * NT_TOT;

    int4 ti = ((const int4*)tets)[t];
    const float* vb = verts + (size_t)b * NV_TOT * 3;
    const float* p0 = vb + (size_t)ti.x * 3;
    const float* p1 = vb + (size_t)ti.y * 3;
    const float* p2 = vb + (size_t)ti.z * 3;
    const float* p3 = vb + (size_t)ti.w * 3;

    float ax = p0[0], ay = p0[1], az = p0[2];
    float bxv = p1[0], byv = p1[1], bzv = p1[2];
    float cxv = p2[0], cyv = p2[1], czv = p2[2];
    float dxv = p3[0], dyv = p3[1], dzv = p3[2];

    float e1x = bxv - ax, e1y = byv - ay, e1z = bzv - az;
    float e2x = cxv - ax, e2y = cyv - ay, e2z = czv - az;
    float e3x = dxv - ax, e3y = dyv - ay, e3z = dzv - az;

    float c23x = e2y * e3z - e2z * e3y;
    float c23y = e2z * e3x - e2x * e3z;
    float c23z = e2x * e3y - e2y * e3x;

    float vol6 = e1x * c23x + e1y * c23y + e1z * c23z;
    if (!(fabsf(vol6) > 1e-12f)) return;
    float iv = 1.0f / vol6;

    int anx  = (int)floorf(fminf(fminf(ax, bxv), fminf(cxv, dxv)) * (float)R);
    int any_ = (int)floorf(fminf(fminf(ay, byv), fminf(cyv, dyv)) * (float)R);
    int anz  = (int)floorf(fminf(fminf(az, bzv), fminf(czv, dzv)) * (float)R);

    unsigned char* occb = g_occ + b * R3;

    #pragma unroll
    for (int k = 0; k < 4; k++) {
        int j = lane + k * 32;
        if (j >= 125) break;
        int t0 = anx + j / 25;
        int t1 = any_ + (j / 5) % 5;
        int t2 = anz + j % 5;
        if ((unsigned)t0 >= R || (unsigned)t1 >= R || (unsigned)t2 >= R) continue;

        float px = ((float)t0 + 0.5f) * (1.0f / (float)R) - ax;
        float py = ((float)t1 + 0.5f) * (1.0f / (float)R) - ay;
        float pz = ((float)t2 + 0.5f) * (1.0f / (float)R) - az;

        float l1 = (px * c23x + py * c23y + pz * c23z) * iv;

        float q1x = py * e3z - pz * e3y;
        float q1y = pz * e3x - px * e3z;
        float q1z = px * e3y - py * e3x;
        float l2 = (q1x * e1x + q1y * e1y + q1z * e1z) * iv;

        float q2x = e2y * pz - e2z * py;
        float q2y = e2z * px - e2x * pz;
        float q2z = e2x * py - e2y * px;
        float l3 = (q2x * e1x + q2y * e1y + q2z * e1z) * iv;

        if (l1 >= 0.0f && l2 >= 0.0f && l3 >= 0.0f && (l1 + l2 + l3) <= 1.0f) {
            occb[(t2 * R + t1) * R + t0] = 1;
        }
    }
}

// ---------------------------------------------------------------------------
// surface splat, block-granular: one (b, vertex) per 256-thread block;
// each thread covers voxel j = tid and j = tid + 256 of the 7^3 window.
// One float4 vector reduction per voxel: (w*c0, w*c1, w*c2, w).
// ---------------------------------------------------------------------------
__device__ __forceinline__ void splat_voxel(int j, int bx, int by, int bz,
                                            float vx, float vy, float vz,
                                            float c0, float c1, float c2,
                                            float4* __restrict__ accb) {
    int s0 = bx + j / 49 - 3;
    int rem = j % 49;
    int s1 = by + rem / 7 - 3;
    int s2 = bz + rem % 7 - 3;
    if ((unsigned)s0 >= R || (unsigned)s1 >= R || (unsigned)s2 >= R) return;

    float dx = ((float)s0 + 0.5f) * (1.0f / (float)R) - vx;
    float dy = ((float)s1 + 0.5f) * (1.0f / (float)R) - vy;
    float dz = ((float)s2 + 0.5f) * (1.0f / (float)R) - vz;
    float d2 = dx * dx + dy * dy + dz * dz;
    float w = __expf(-d2 * INV2SIG2);

    int vox = (s2 * R + s1) * R + s0;
    red_add_f32x4(&accb[vox], w * c0, w * c1, w * c2, w);
}

__device__ __forceinline__ void splat_work(int blk, int tid,
                                           const float* __restrict__ verts,
                                           const float* __restrict__ code) {
    int b = blk / NSURF_N;
    int v = blk - b * NSURF_N;

    const float* vp = verts + ((size_t)b * NV_TOT + v) * 3;
    float vx = vp[0], vy = vp[1], vz = vp[2];
    const float* cp = code + ((size_t)b * NSURF_N + v) * 3;
    float c0 = cp[0], c1 = cp[1], c2 = cp[2];

    int bx = (int)floorf(vx * (float)R);
    int by = (int)floorf(vy * (float)R);
    int bz = (int)floorf(vz * (float)R);

    float4* accb = g_acc + b * R3;

    splat_voxel(tid, bx, by, bz, vx, vy, vz, c0, c1, c2, accb);
    if (tid < 343 - TPB)
        splat_voxel(tid + TPB, bx, by, bz, vx, vy, vz, c0, c1, c2, accb);
}

// ---------------------------------------------------------------------------
// fused work kernel: blocks [0, TET_BLOCKS) do tets, the rest do splats.
// The two phases write disjoint buffers, so they need no ordering and the
// block scheduler overlaps them across the chip.
// ---------------------------------------------------------------------------
__global__ void __launch_bounds__(TPB)
work_kernel(const float* __restrict__ verts,
            const float* __restrict__ code,
            const int*   __restrict__ tets) {
    int blk = blockIdx.x;
    if (blk < TET_BLOCKS) {
        int gw = blk * TETS_PER_BLK + (threadIdx.x >> 5);
        if (gw < BATCH * NT_TOT)
            tet_work(gw, threadIdx.x & 31, verts, tets);
    } else {
        splat_work(blk - TET_BLOCKS, threadIdx.x, verts, code);
    }
}

// ---------------------------------------------------------------------------
// finalize: out[b,c,vox] = acc.c / acc.w * occ. 4 voxels per thread.
// ---------------------------------------------------------------------------
__global__ void finalize_kernel(float* __restrict__ out) {
    int i = blockIdx.x * blockDim.x + threadIdx.x;   // 4-voxel group
    if (i >= BATCH * R3 / 4) return;
    int gi  = i * 4;
    int b   = gi >> 21;
    int vox = gi & (R3 - 1);

    uchar4 oc = ((const uchar4*)g_occ)[i];
    const float4* a = g_acc + gi;
    float4 a0 = a[0], a1 = a[1], a2 = a[2], a3 = a[3];

    float s0 = (float)oc.x / a0.w;
    float s1 = (float)oc.y / a1.w;
    float s2 = (float)oc.z / a2.w;
    float s3 = (float)oc.w / a3.w;

    float* ob = out + (size_t)b * 3 * R3 + vox;
    *(float4*)(ob)          = make_float4(a0.x * s0, a1.x * s1, a2.x * s2, a3.x * s3);
    *(float4*)(ob + R3)     = make_float4(a0.y * s0, a1.y * s1, a2.y * s2, a3.y * s3);
    *(float4*)(ob + 2 * R3) = make_float4(a0.z * s0, a1.z * s1, a2.z * s2, a3.z * s3);
}

// ---------------------------------------------------------------------------
extern "C" void kernel_launch(void* const* d_in, const int* in_sizes, int n_in,
                              void* d_out, int out_size) {
    const float* smpl_vertices = (const float*)d_in[0]; // (2, 7700, 3)
    const float* vertex_code   = (const float*)d_in[1]; // (2, 6890, 3)
    // d_in[2] = face_indices — dead code in the reference, unused.
    const int*   tet_indices   = (const int*)d_in[3];   // (30000, 4)
    float* out = (float*)d_out;                         // (2, 3, 128, 128, 128)

    {
        int n = BATCH * R3 / 4;
        init_kernel<<<(n + TPB - 1) / TPB, TPB>>>();
    }
    work_kernel<<<TET_BLOCKS + SPLAT_BLOCKS, TPB>>>(smpl_vertices, vertex_code,
                                                    tet_indices);
    {
        int n = BATCH * R3 / 4;
        finalize_kernel<<<(n + TPB - 1) / TPB, TPB>>>(out);
    }
}